// round 3
// baseline (speedup 1.0000x reference)
#include <cuda_runtime.h>

// N=8192 rows, C=5000 classes, RATIO=3
#define NC   5000
#define NT   256
#define NW   8
#define NB   2048   // 11-bit bins: sign + 8 exp + 2 mantissa
#define CAP  1024   // threshold-bin candidate capacity (expected ~120)

__device__ double   g_loss = 0.0;
__device__ double   g_tsum = 0.0;
__device__ unsigned g_done = 0;

// order-preserving float->uint key (larger float <-> larger key)
__device__ __forceinline__ unsigned fkey(float f) {
    unsigned b = __float_as_uint(f);
    return (b & 0x80000000u) ? ~b : (b | 0x80000000u);
}
__device__ __forceinline__ float kinv(unsigned k) {
    return __uint_as_float((k & 0x80000000u) ? (k & 0x7FFFFFFFu) : ~k);
}
// fast softplus (MUFU-based)
__device__ __forceinline__ float sp(float x) {
    float l = __logf(1.f + __expf(-fabsf(x)));
    return x > 0.f ? x + l : l;
}

__global__ void __launch_bounds__(NT)
hardneg(const float* __restrict__ pred, const float* __restrict__ target,
        float* __restrict__ out)
{
    __shared__ unsigned s_key[NC];    // 20000 B: keys (0 marker for positives)
    __shared__ unsigned s_hist[NB];   //  8192 B: lo16 = all count, hi16 = pos count
    __shared__ unsigned s_cand[CAP];  //  4096 B
    __shared__ unsigned s_wsum[NW];
    __shared__ float    s_accr[NW];
    __shared__ unsigned s_binv, s_kkv, s_tkey, s_krem;
    __shared__ int      s_cnt;

    const int tid  = threadIdx.x;
    const int lane = tid & 31;
    const int wid  = tid >> 5;
    const int row  = blockIdx.x;

    const float4* p4 = (const float4*)(pred   + (size_t)row * NC);
    const float4* t4 = (const float4*)(target + (size_t)row * NC);

    // zero histogram (vectorized)
    uint4* h4 = (uint4*)s_hist;
    #pragma unroll
    for (int j = 0; j < NB / 4 / NT; j++) h4[tid + j * NT] = make_uint4(0, 0, 0, 0);
    if (tid == 0) s_cnt = 0;
    __syncthreads();

    // ---- pass A: load, key, match-aggregated histogram, positive BCE ----
    float accP = 0.f;
    uint4* k4s = (uint4*)s_key;

    #define PROC(px, tx, kout)                                                \
        do {                                                                  \
            float    _x = (px);                                               \
            unsigned _k = fkey(_x);                                           \
            unsigned _b = _k >> 21;                                           \
            unsigned _am = __activemask();                                    \
            unsigned _mm = __match_any_sync(_am, _b);                         \
            if ((_mm & ((1u << lane) - 1u)) == 0u)                            \
                atomicAdd(&s_hist[_b], (unsigned)__popc(_mm));                \
            bool _p = ((tx) != 0.f);                                          \
            if (_p) { accP += sp(_x) - _x; atomicAdd(&s_hist[_b], 65536u); }  \
            (kout) = _p ? 0u : _k;                                            \
        } while (0)

    for (int i = tid; i < NC / 4; i += NT) {
        float4 p = p4[i];
        float4 t = t4[i];
        uint4  k;
        PROC(p.x, t.x, k.x);
        PROC(p.y, t.y, k.y);
        PROC(p.z, t.z, k.z);
        PROC(p.w, t.w, k.w);
        k4s[i] = k;
    }
    #undef PROC
    __syncthreads();

    // ---- suffix scan over packed (all,pos) counts; thread owns 8 bins ----
    unsigned w8[8];
    unsigned S = 0;  // packed: lo = all in my 8 bins, hi = pos in my 8 bins
    #pragma unroll
    for (int j = 0; j < 8; j++) {
        unsigned v = s_hist[tid * 8 + j];
        w8[j] = v;
        S += v;  // packed add safe: each half <= 5000 < 65536
    }
    unsigned v = S;  // inclusive suffix within warp (packed)
    #pragma unroll
    for (int off = 1; off < 32; off <<= 1) {
        unsigned o = __shfl_down_sync(0xFFFFFFFFu, v, off);
        if (lane + off < 32) v += o;
    }
    if (lane == 0) s_wsum[wid] = v;
    __syncthreads();

    unsigned tot = 0;
    #pragma unroll
    for (int w = 0; w < NW; w++) tot += s_wsum[w];
    const int post = (int)(tot >> 16);                 // total positives (free!)
    int k0 = 3 * post;
    if (k0 > NC - post) k0 = NC - post;

    unsigned abv = v - S;                              // packed above within warp
    #pragma unroll
    for (int w = wid + 1; w < NW; w++) abv += s_wsum[w];
    const unsigned negAbove = (abv & 0xFFFFu) - (abv >> 16);
    const unsigned negMine  = (S   & 0xFFFFu) - (S   >> 16);

    if (k0 > 0) {
        unsigned kk = (unsigned)k0;
        if (negAbove < kk && kk <= negAbove + negMine) {
            unsigned a = negAbove;
            #pragma unroll
            for (int j = 7; j >= 0; j--) {             // walk my bins from the top
                unsigned wv = w8[j];
                unsigned c  = (wv & 0xFFFFu) - (wv >> 16);
                if (kk <= a + c) { s_binv = (unsigned)(tid * 8 + j); s_kkv = kk - a; break; }
                a += c;
            }
        }
    }
    __syncthreads();

    // ---- pass B (fused): sum above-bin softplus + gather threshold-bin candidates ----
    float acc = accP;
    if (k0 > 0) {
        const unsigned bsel = s_binv;
        const uint4* kr = (const uint4*)s_key;
        #define G(kc)                                                          \
            do {                                                               \
                unsigned _b = (kc) >> 21;                                      \
                if (_b > bsel) acc += sp(kinv(kc));                            \
                else if (_b == bsel && (kc) != 0u) {                           \
                    int s = atomicAdd(&s_cnt, 1);                              \
                    if (s < CAP) s_cand[s] = (kc);                             \
                }                                                              \
            } while (0)
        for (int i = tid; i < NC / 4; i += NT) {
            uint4 kv = kr[i];
            G(kv.x); G(kv.y); G(kv.z); G(kv.w);
        }
        #undef G
    }
    __syncthreads();

    // ---- exact k-th largest among candidates (rank counting) ----
    if (k0 > 0) {
        int M = s_cnt; if (M > CAP) M = CAP;
        const unsigned kk = s_kkv;
        for (int c = tid; c < M; c += NT) {
            unsigned key = s_cand[c];
            unsigned gt = 0, eq = 0;
            for (int j = 0; j < M; j++) {
                unsigned o = s_cand[j];
                gt += (o > key);
                eq += (o == key);
            }
            if (gt < kk && kk <= gt + eq) { s_tkey = key; s_krem = kk - gt; }
        }
    }
    __syncthreads();

    // ---- in-bin selected candidates ----
    if (k0 > 0) {
        const unsigned tk = s_tkey;
        int M = s_cnt; if (M > CAP) M = CAP;
        for (int c = tid; c < M; c += NT) {
            unsigned key = s_cand[c];
            if (key > tk) acc += sp(kinv(key));
        }
    }

    // ---- block reduce + global accumulate + last-block finalize ----
    #pragma unroll
    for (int off = 16; off; off >>= 1) acc += __shfl_down_sync(0xFFFFFFFFu, acc, off);
    if (lane == 0) s_accr[wid] = acc;
    __syncthreads();

    if (tid == 0) {
        float totL = 0.f;
        #pragma unroll
        for (int w = 0; w < NW; w++) totL += s_accr[w];
        if (k0 > 0) totL += (float)s_krem * sp(kinv(s_tkey));  // exact tie correction
        atomicAdd(&g_loss, (double)totL);
        atomicAdd(&g_tsum, (double)post);
        __threadfence();
        unsigned done = atomicAdd(&g_done, 1u);
        if (done == gridDim.x - 1) {
            double L = atomicAdd(&g_loss, 0.0);   // forced memory reads
            double T = atomicAdd(&g_tsum, 0.0);
            out[0] = (float)(L / T);
            // reset for next (deterministic across graph replays)
            atomicExch((unsigned long long*)&g_loss, 0ull);
            atomicExch((unsigned long long*)&g_tsum, 0ull);
            __threadfence();
            atomicExch(&g_done, 0u);
        }
    }
}

extern "C" void kernel_launch(void* const* d_in, const int* in_sizes, int n_in,
                              void* d_out, int out_size) {
    const float* pred   = (const float*)d_in[0];
    const float* target = (const float*)d_in[1];
    float* out = (float*)d_out;
    int rows = in_sizes[0] / NC;

    hardneg<<<rows, NT>>>(pred, target, out);
}

// round 4
// speedup vs baseline: 2.1118x; 2.1118x over previous
#include <cuda_runtime.h>

// N=8192 rows, C=5000 classes, RATIO=3
#define NC   5000
#define NT   256
#define NW   8
#define HW   2048   // histogram words: 4096 bins, two 16-bit counts per word
#define CAP  1024   // threshold-bin candidate capacity (expected ~50-120)

__device__ double   g_loss = 0.0;
__device__ double   g_tsum = 0.0;
__device__ unsigned g_done = 0;

// order-preserving float->uint key (larger float <-> larger key)
__device__ __forceinline__ unsigned fkey(float f) {
    unsigned b = __float_as_uint(f);
    return (b & 0x80000000u) ? ~b : (b | 0x80000000u);
}
__device__ __forceinline__ float kinv(unsigned k) {
    return __uint_as_float((k & 0x80000000u) ? (k & 0x7FFFFFFFu) : ~k);
}
// fast softplus (MUFU-based)
__device__ __forceinline__ float sp(float x) {
    float l = __logf(1.f + __expf(-fabsf(x)));
    return x > 0.f ? x + l : l;
}

__global__ void __launch_bounds__(NT)
hardneg(const float* __restrict__ pred, const float* __restrict__ target,
        float* __restrict__ out)
{
    __shared__ unsigned s_key[NC];     // 20000 B : keys (0 marker for positives)
    __shared__ unsigned s_hist[HW];    //  8192 B : packed 16-bit counts (4096 bins)
    __shared__ unsigned s_cand[CAP];   //  4096 B
    __shared__ unsigned s_wsum[NW];
    __shared__ int      s_posr[NW];
    __shared__ float    s_accr[NW];
    __shared__ unsigned s_binv, s_kkv, s_tkey, s_krem;
    __shared__ int      s_cnt;

    const int tid  = threadIdx.x;
    const int lane = tid & 31;
    const int wid  = tid >> 5;
    const int row  = blockIdx.x;

    const float4* p4 = (const float4*)(pred   + (size_t)row * NC);
    const float4* t4 = (const float4*)(target + (size_t)row * NC);

    // zero histogram (vectorized)
    uint4* h4 = (uint4*)s_hist;
    #pragma unroll
    for (int j = 0; j < HW / 4 / NT; j++) h4[tid + j * NT] = make_uint4(0, 0, 0, 0);
    if (tid == 0) s_cnt = 0;
    __syncthreads();

    // ---- pass A: load, classify, key, histogram (negatives), positive BCE ----
    int   poscnt = 0;
    float accP   = 0.f;
    uint4* k4s = (uint4*)s_key;

    #define PROC(px, tx, kout)                                             \
        do {                                                               \
            float _x = (px);                                               \
            if ((tx) != 0.f) {                                             \
                poscnt++; accP += sp(_x) - _x; (kout) = 0u;                \
            } else {                                                       \
                unsigned _k = fkey(_x); (kout) = _k;                       \
                atomicAdd(&s_hist[_k >> 21],                               \
                          ((_k >> 20) & 1u) ? 65536u : 1u);                \
            }                                                              \
        } while (0)

    for (int i = tid; i < NC / 4; i += NT) {
        float4 p = p4[i];
        float4 t = t4[i];
        uint4  k;
        PROC(p.x, t.x, k.x);
        PROC(p.y, t.y, k.y);
        PROC(p.z, t.z, k.z);
        PROC(p.w, t.w, k.w);
        k4s[i] = k;
    }
    #undef PROC
    __syncthreads();

    // ---- locate threshold bin: suffix counts via shuffle scan ----
    // thread t owns bins [t*16, t*16+16) = words [t*8, t*8+8)
    unsigned w8[8];
    unsigned S = 0;
    #pragma unroll
    for (int j = 0; j < 8; j++) {
        unsigned v = s_hist[tid * 8 + j];
        w8[j] = v;
        S += (v & 0xFFFFu) + (v >> 16);
    }
    unsigned v = S;  // inclusive suffix within warp
    #pragma unroll
    for (int off = 1; off < 32; off <<= 1) {
        unsigned o = __shfl_down_sync(0xFFFFFFFFu, v, off);
        if (lane + off < 32) v += o;
    }
    if (lane == 0) s_wsum[wid] = v;

    int pc = poscnt;
    #pragma unroll
    for (int off = 16; off; off >>= 1) pc += __shfl_down_sync(0xFFFFFFFFu, pc, off);
    if (lane == 0) s_posr[wid] = pc;
    __syncthreads();

    int post = 0;
    #pragma unroll
    for (int w = 0; w < NW; w++) post += s_posr[w];
    int k0 = 3 * post;
    if (k0 > NC - post) k0 = NC - post;

    unsigned above = v - S;  // bins above mine within my warp
    #pragma unroll
    for (int w = wid + 1; w < NW; w++) above += s_wsum[w];

    if (k0 > 0) {
        unsigned kk = (unsigned)k0;
        if (above < kk && kk <= above + S) {
            unsigned a = above;
            #pragma unroll
            for (int j = 15; j >= 0; j--) {   // walk my 16 bins from the top
                unsigned wv = w8[j >> 1];
                unsigned c  = (j & 1) ? (wv >> 16) : (wv & 0xFFFFu);
                if (kk <= a + c) { s_binv = (unsigned)(tid * 16 + j); s_kkv = kk - a; break; }
                a += c;
            }
        }
    }
    __syncthreads();

    // ---- pass B (fused): sum above-bin softplus + gather threshold-bin candidates ----
    float acc = accP;
    if (k0 > 0) {
        const unsigned bsel = s_binv;
        const uint4* kr = (const uint4*)s_key;
        #define G(kc)                                                          \
            do {                                                               \
                unsigned _b = (kc) >> 20;                                      \
                if (_b > bsel) acc += sp(kinv(kc));                            \
                else if (_b == bsel && (kc) != 0u) {                           \
                    int s = atomicAdd(&s_cnt, 1);                              \
                    if (s < CAP) s_cand[s] = (kc);                             \
                }                                                              \
            } while (0)
        for (int i = tid; i < NC / 4; i += NT) {
            uint4 kv = kr[i];
            G(kv.x); G(kv.y); G(kv.z); G(kv.w);
        }
        #undef G
    }
    __syncthreads();

    // ---- exact k-th largest among candidates (rank counting) ----
    if (k0 > 0) {
        int M = s_cnt; if (M > CAP) M = CAP;
        const unsigned kk = s_kkv;
        for (int c = tid; c < M; c += NT) {
            unsigned key = s_cand[c];
            unsigned gt = 0, eq = 0;
            for (int j = 0; j < M; j++) {
                unsigned o = s_cand[j];
                gt += (o > key);
                eq += (o == key);
            }
            if (gt < kk && kk <= gt + eq) { s_tkey = key; s_krem = kk - gt; }
        }
    }
    __syncthreads();

    // ---- in-bin selected candidates ----
    if (k0 > 0) {
        const unsigned tk = s_tkey;
        int M = s_cnt; if (M > CAP) M = CAP;
        for (int c = tid; c < M; c += NT) {
            unsigned key = s_cand[c];
            if (key > tk) acc += sp(kinv(key));
        }
    }

    // ---- block reduce + global accumulate + last-block finalize ----
    #pragma unroll
    for (int off = 16; off; off >>= 1) acc += __shfl_down_sync(0xFFFFFFFFu, acc, off);
    if (lane == 0) s_accr[wid] = acc;
    __syncthreads();

    if (tid == 0) {
        float totL = 0.f;
        #pragma unroll
        for (int w = 0; w < NW; w++) totL += s_accr[w];
        if (k0 > 0) totL += (float)s_krem * sp(kinv(s_tkey));  // exact tie correction
        atomicAdd(&g_loss, (double)totL);
        atomicAdd(&g_tsum, (double)post);
        __threadfence();
        unsigned done = atomicAdd(&g_done, 1u);
        if (done == gridDim.x - 1) {
            double L = atomicAdd(&g_loss, 0.0);   // forced memory reads
            double T = atomicAdd(&g_tsum, 0.0);
            out[0] = (float)(L / T);
            // reset for next graph replay (deterministic)
            atomicExch((unsigned long long*)&g_loss, 0ull);
            atomicExch((unsigned long long*)&g_tsum, 0ull);
            __threadfence();
            atomicExch(&g_done, 0u);
        }
    }
}

extern "C" void kernel_launch(void* const* d_in, const int* in_sizes, int n_in,
                              void* d_out, int out_size) {
    const float* pred   = (const float*)d_in[0];
    const float* target = (const float*)d_in[1];
    float* out = (float*)d_out;
    int rows = in_sizes[0] / NC;

    hardneg<<<rows, NT>>>(pred, target, out);
}